// round 10
// baseline (speedup 1.0000x reference)
#include <cuda_runtime.h>
#include <math.h>

// output_spikes (B=16, T=2000, N=512) float32, target_cv (512) float32.
#define NNEUR 512
#define NG    128                  // neuron groups of 4 (float4)
#define LTOT  32000                // B*T
#define NBLK  296                  // 2 blocks/SM, single wave
#define SUBS  (NBLK * 4)           // 1184 sub-chunks (4 row-slices per block)
#define RB    (LTOT / SUBS)        // 27
#define RREM  (LTOT % SUBS)        // 32 (sub-chunks 0..31 get 28 rows; uniform per block)
#define RED_THREADS 512            // pow2 >= NBLK for the pass-2 tree

#define DEPTH 3                    // cp.async pipeline stages
#define SROWS 2                    // rows per stage
#define STAGE_BYTES (4 * SROWS * 128 * 16)   // 16384 B per stage
#define ROW_BYTES   (128 * 16)               // 2048 B per row within a slice

typedef unsigned long long u64;

// packed {1.0f,1.0f} and {-1.0f,-1.0f}
#define ONE2_C   0x3F8000003F800000ULL
#define NEG12_C  0xBF800000BF800000ULL

#define F2_ADD(o, a, b)    asm("add.rn.f32x2 %0, %1, %2;" : "=l"(o) : "l"(a), "l"(b))
#define F2_MUL(o, a, b)    asm("mul.rn.f32x2 %0, %1, %2;" : "=l"(o) : "l"(a), "l"(b))
#define F2_FMA(o, a, b, c) asm("fma.rn.f32x2 %0, %1, %2, %3;" : "=l"(o) : "l"(a), "l"(b), "l"(c))
#define F2_PACK(o, lo, hi) asm("mov.b64 %0, {%1, %2};" : "=l"(o) : "f"(lo), "f"(hi))
#define F2_UNPACK(lo, hi, in) asm("mov.b64 {%0, %1}, %2;" : "=f"(lo), "=f"(hi) : "l"(in))

#define CP_ASYNC16(dst, src) \
    asm volatile("cp.async.cg.shared.global [%0], [%1], 16;" :: "r"(dst), "l"(src) : "memory")
#define CP_COMMIT()  asm volatile("cp.async.commit_group;" ::: "memory")
#define CP_WAIT2()   asm volatile("cp.async.wait_group 2;" ::: "memory")
#define CP_WAIT0()   asm volatile("cp.async.wait_group 0;" ::: "memory")

// Per-(neuron, block) partial: {k, first_spike_l, last_spike_l, bits(sum_d2)}
__device__ int4  g_partial[NNEUR * NBLK];
__device__ float g_accum;
__device__ int   g_cnt;

// Ordered combine of two ADJACENT segments (a before b). Identity: k == 0.
__device__ __forceinline__ int4 comb(int4 a, int4 b) {
    if (b.x == 0) return a;
    if (a.x == 0) return b;
    float d = (float)(b.y - a.z);                       // cross-segment ISI
    float s = __int_as_float(a.w) + __int_as_float(b.w) + d * d;
    return make_int4(a.x + b.x, a.y, b.z, __float_as_int(s));
}

// Packed update for one neuron pair p. v in {0,1} per lane.
// gp: gap counter; s: sum d^2 (incl. bogus first gap); kf: spike count;
// ns: 1 until first spike then 0; lz: #rows before first spike.
#define PEP(p, vlo, vhi)                         \
    do {                                         \
        u64 v2_, d2_, m2_;                       \
        F2_PACK(v2_, (vlo), (vhi));              \
        F2_ADD(d2_, gp2[p], one2);               \
        F2_MUL(m2_, v2_, d2_);                   \
        F2_FMA(s2[p], m2_, d2_, s2[p]);          \
        F2_FMA(gp2[p], m2_, neg12, d2_);         \
        F2_ADD(kf2[p], kf2[p], v2_);             \
        F2_FMA(ns2[p], v2_, neg_ns2(p), ns2[p]); \
        F2_ADD(lz2[p], lz2[p], ns2[p]);          \
    } while (0)

// ns_new = ns - v*ns  -> fma(v, -ns, ns). Need -ns as operand:
#define neg_ns2(p) nns2[p]

#define PROW(vec)                      \
    do {                               \
        PEP(0, (vec).x, (vec).y);      \
        PEP(1, (vec).z, (vec).w);      \
        /* refresh -ns after updates */ \
        F2_MUL(nns2[0], ns2[0], neg12); \
        F2_MUL(nns2[1], ns2[1], neg12); \
    } while (0)

__global__ __launch_bounds__(512, 2) void cv_pass1(const float* __restrict__ x) {
    __shared__ float4 sbuf[DEPTH][4][SROWS][128];   // 48 KB

    const int tid   = threadIdx.x;
    const int slice = tid >> 7;          // 0..3 : row-slice within block
    const int g     = tid & (NG - 1);    // 0..127: neuron group (4 neurons)
    const int sc    = blockIdx.x * 4 + slice;      // global sub-chunk
    if (blockIdx.x == 0 && tid == 0) { g_accum = 0.0f; g_cnt = 0; }

    const int start = sc * RB + min(sc, RREM);
    const int R     = RB + (sc < RREM ? 1 : 0);    // 27 or 28, uniform per block
    const int NST   = (R + SROWS - 1) / SROWS;     // 14

    const u64 one2  = ONE2_C;
    const u64 neg12 = NEG12_C;
    u64 gp2[2]  = {0ULL, 0ULL};
    u64 s2[2]   = {0ULL, 0ULL};
    u64 kf2[2]  = {0ULL, 0ULL};
    u64 ns2[2]  = {ONE2_C, ONE2_C};
    u64 nns2[2] = {NEG12_C, NEG12_C};
    u64 lz2[2]  = {0ULL, 0ULL};

    const float4* gbase = (const float4*)x + (size_t)start * NG + g;
    const unsigned int sbase =
        (unsigned int)__cvta_generic_to_shared(&sbuf[0][slice][0][g]);

    // issue a stage: rows 2*st, 2*st+1 (guarded), one commit group
#define ISSUE(st)                                                       \
    do {                                                                \
        const int b_   = (st) % DEPTH;                                  \
        const int r0_  = (st) * SROWS;                                  \
        unsigned int d_ = sbase + b_ * STAGE_BYTES;                     \
        if (r0_ < R)     CP_ASYNC16(d_,             gbase + (size_t)r0_ * NG);       \
        if (r0_ + 1 < R) CP_ASYNC16(d_ + ROW_BYTES, gbase + (size_t)(r0_ + 1) * NG); \
        CP_COMMIT();                                                    \
    } while (0)

    ISSUE(0);
    ISSUE(1);

    for (int st = 0; st < NST; ++st) {
        if (st + 2 < NST) { ISSUE(st + 2); } else { CP_COMMIT(); }
        CP_WAIT2();                                   // stage st resident
        const int b  = st % DEPTH;
        const int r0 = st * SROWS;
        {
            float4 v = sbuf[b][slice][0][g];
            PROW(v);
        }
        if (r0 + 1 < R) {
            float4 v = sbuf[b][slice][1][g];
            PROW(v);
        }
    }
    CP_WAIT0();

    // Flush: t_first = lz+1, t_last = R - gp (1-based local);
    // subtract bogus first gap^2 (= t_first^2) from s.
    __syncthreads();                                  // before aliasing sbuf
    int4* sp = (int4*)sbuf;                           // [4][NNEUR] view, 32 KB
#pragma unroll
    for (int pr = 0; pr < 2; ++pr) {
        float kfl, kfh, gpl, gph, ssl, ssh, lzl, lzh;
        F2_UNPACK(kfl, kfh, kf2[pr]);
        F2_UNPACK(gpl, gph, gp2[pr]);
        F2_UNPACK(ssl, ssh, s2[pr]);
        F2_UNPACK(lzl, lzh, lz2[pr]);
        float kfj[2] = {kfl, kfh}, gpj[2] = {gpl, gph};
        float ssj[2] = {ssl, ssh}, lzj[2] = {lzl, lzh};
#pragma unroll
        for (int h = 0; h < 2; ++h) {
            const int j = pr * 2 + h;
            int kk = (int)kfj[h];
            int4 part;
            if (kk > 0) {
                float tf1 = lzj[h] + 1.0f;            // t_first, 1-based local
                int tlast = R - (int)gpj[h];          // 1-based local
                float sc_ = ssj[h] - tf1 * tf1;
                part = make_int4(kk, start + (int)lzj[h], start + tlast - 1,
                                 __float_as_int(sc_));
            } else {
                part = make_int4(0, 0, 0, 0);
            }
            sp[slice * NNEUR + g * 4 + j] = part;
        }
    }
    __syncthreads();

    if (slice == 0) {
#pragma unroll
        for (int j = 0; j < 4; ++j) {
            const int n = g * 4 + j;
            int4 a = sp[0 * NNEUR + n];
            a = comb(a, sp[1 * NNEUR + n]);
            a = comb(a, sp[2 * NNEUR + n]);
            a = comb(a, sp[3 * NNEUR + n]);
            g_partial[(size_t)n * NBLK + blockIdx.x] = a;
        }
    }
#undef ISSUE
}

// One block per neuron: adjacent-pair tree over the 296 block partials.
__global__ __launch_bounds__(RED_THREADS) void cv_pass2(const float* __restrict__ target) {
    const int n   = blockIdx.x;
    const int tid = threadIdx.x;

    __shared__ int4 sm[RED_THREADS];

    int4 part = make_int4(0, 0, 0, 0);
    if (tid < NBLK)
        part = g_partial[(size_t)n * NBLK + tid];   // coalesced along chunk axis
    sm[tid] = part;
    __syncthreads();

    for (int lvl = RED_THREADS; lvl > 1; lvl >>= 1) {
        const int half = lvl >> 1;
        int4 res;
        if (tid < half)
            res = comb(sm[2 * tid], sm[2 * tid + 1]);   // adjacent -> contiguous
        __syncthreads();
        if (tid < half)
            sm[tid] = res;
        __syncthreads();
    }

    if (tid == 0) {
        int4 tot = sm[0];
        int kk = tot.x;
        if (kk >= 3) {
            float cnt   = (float)(kk - 1);            // number of ISIs
            float sum_d = (float)(tot.z - tot.y);     // telescoping sum of ISIs
            float mean  = sum_d / cnt;
            if (mean > 0.0f) {
                // sum((d-mean)^2) = sum_d2 - 2*mean*sum_d + cnt*mean^2
                float var = (__int_as_float(tot.w) - 2.0f * mean * sum_d + cnt * mean * mean)
                            / fmaxf(cnt - 1.0f, 1.0f);   // unbiased (correction=1)
                float stdv = (var > 0.0f) ? sqrtf(var) : 0.0f;
                float cv   = stdv / fmaxf(mean, 1e-12f);
                float diff = cv - target[n];
                atomicAdd(&g_accum, diff * diff);
                atomicAdd(&g_cnt, 1);
            }
        }
    }
}

__global__ void cv_pass3(float* __restrict__ out) {
    out[0] = g_accum / fmaxf((float)g_cnt, 1.0f);
}

extern "C" void kernel_launch(void* const* d_in, const int* in_sizes, int n_in,
                              void* d_out, int out_size) {
    const float* spikes = (const float*)d_in[0];   // (16, 2000, 512) float32
    const float* target = (const float*)d_in[1];   // (512,) float32
    float* out = (float*)d_out;                    // scalar float32

    cv_pass1<<<NBLK, 512>>>(spikes);
    cv_pass2<<<NNEUR, RED_THREADS>>>(target);
    cv_pass3<<<1, 1>>>(out);
}

// round 12
// speedup vs baseline: 1.0017x; 1.0017x over previous
#include <cuda_runtime.h>
#include <math.h>

// output_spikes (B=16, T=2000, N=512) float32, target_cv (512) float32.
#define NNEUR 512
#define NG    128                  // neuron groups of 4 (float4)
#define LTOT  32000                // B*T
#define NBLK  296                  // 2 blocks/SM, single wave
#define SUBS  (NBLK * 4)           // 1184 sub-chunks (4 row-slices per block)
#define RB    (LTOT / SUBS)        // 27
#define RREM  (LTOT % SUBS)        // 32 (sub-chunks 0..31 get 28 rows)
#define RED_THREADS 512            // pow2 >= NBLK for the pass-2 tree

typedef unsigned long long u64;

// packed {1.0f,1.0f} and {-1.0f,-1.0f}
#define ONE2_C   0x3F8000003F800000ULL
#define NEG12_C  0xBF800000BF800000ULL

#define F2_ADD(o, a, b)    asm("add.rn.f32x2 %0, %1, %2;" : "=l"(o) : "l"(a), "l"(b))
#define F2_MUL(o, a, b)    asm("mul.rn.f32x2 %0, %1, %2;" : "=l"(o) : "l"(a), "l"(b))
#define F2_FMA(o, a, b, c) asm("fma.rn.f32x2 %0, %1, %2, %3;" : "=l"(o) : "l"(a), "l"(b), "l"(c))
#define F2_PACK(o, lo, hi) asm("mov.b64 %0, {%1, %2};" : "=l"(o) : "f"(lo), "f"(hi))
#define F2_UNPACK(lo, hi, in) asm("mov.b64 {%0, %1}, %2;" : "=f"(lo), "=f"(hi) : "l"(in))

// Per-(neuron, block) partial: {k, first_spike_l, last_spike_l, bits(sum_d2)}
__device__ int4  g_partial[NNEUR * NBLK];
__device__ float g_accum;
__device__ int   g_cnt;
__device__ int   g_ticket;

// Ordered combine of two ADJACENT segments (a before b). Identity: k == 0.
__device__ __forceinline__ int4 comb(int4 a, int4 b) {
    if (b.x == 0) return a;
    if (a.x == 0) return b;
    float d = (float)(b.y - a.z);                       // cross-segment ISI
    float s = __int_as_float(a.w) + __int_as_float(b.w) + d * d;
    return make_int4(a.x + b.x, a.y, b.z, __float_as_int(s));
}

// Packed update for one neuron pair p. v in {0,1} per lane.
// gp: gap counter; s: sum d^2 (incl. bogus first gap); kf: spike count;
// ns: 1 until first spike then 0; lz: #rows before first spike.
#define PEP(p, vlo, vhi)                         \
    do {                                         \
        u64 v2_, d2_, m2_, t2_;                  \
        F2_PACK(v2_, (vlo), (vhi));              \
        F2_ADD(d2_, gp2[p], one2);               \
        F2_MUL(m2_, v2_, d2_);                   \
        F2_FMA(s2[p], m2_, d2_, s2[p]);          \
        F2_FMA(gp2[p], m2_, neg12, d2_);         \
        F2_ADD(kf2[p], kf2[p], v2_);             \
        F2_MUL(t2_, v2_, ns2[p]);                \
        F2_FMA(ns2[p], t2_, neg12, ns2[p]);      \
        F2_ADD(lz2[p], lz2[p], ns2[p]);          \
    } while (0)

#define PROW(vec)                      \
    do {                               \
        PEP(0, (vec).x, (vec).y);      \
        PEP(1, (vec).z, (vec).w);      \
    } while (0)

__global__ __launch_bounds__(512, 2) void cv_pass1(const float* __restrict__ x) {
    const int tid   = threadIdx.x;
    const int slice = tid >> 7;          // 0..3 : row-slice within block
    const int g     = tid & (NG - 1);    // 0..127: neuron group (4 neurons)
    const int sc    = blockIdx.x * 4 + slice;      // global sub-chunk
    if (blockIdx.x == 0 && tid == 0) { g_accum = 0.0f; g_cnt = 0; g_ticket = 0; }

    const int start = sc * RB + min(sc, RREM);
    const int rows  = RB + (sc < RREM ? 1 : 0);    // 27 or 28

    const u64 one2  = ONE2_C;
    const u64 neg12 = NEG12_C;
    u64 gp2[2] = {0ULL, 0ULL};
    u64 s2[2]  = {0ULL, 0ULL};
    u64 kf2[2] = {0ULL, 0ULL};
    u64 ns2[2] = {ONE2_C, ONE2_C};
    u64 lz2[2] = {0ULL, 0ULL};

    const float4* p = (const float4*)x + (size_t)start * NG + g;
    int r = 0;

    // prefetch batch 0 (rows >= 27 > 4 always); nc/texture path
    float4 b0 = __ldg(p + 0 * NG), b1 = __ldg(p + 1 * NG);
    float4 b2 = __ldg(p + 2 * NG), b3 = __ldg(p + 3 * NG);
    p += 4 * NG;

    while (r + 8 <= rows) {
        // prefetch next batch BEFORE processing current (loads stay in flight)
        float4 c0 = __ldg(p + 0 * NG), c1 = __ldg(p + 1 * NG);
        float4 c2 = __ldg(p + 2 * NG), c3 = __ldg(p + 3 * NG);
        p += 4 * NG;
        PROW(b0); PROW(b1); PROW(b2); PROW(b3);
        b0 = c0; b1 = c1; b2 = c2; b3 = c3;
        r += 4;
    }
    // drain prefetched batch
    PROW(b0); PROW(b1); PROW(b2); PROW(b3);
    r += 4;
    // tail (0..3 rows)
    for (; r < rows; ++r) {
        float4 v = __ldg(p);
        p += NG;
        PROW(v);
    }

    // Flush: t_first = lz+1, t_last = rows - gp (1-based local);
    // subtract bogus first gap^2 (= t_first^2) from s.
    __shared__ int4 sp[4][NNEUR];
#pragma unroll
    for (int pr = 0; pr < 2; ++pr) {
        float kfl, kfh, gpl, gph, ssl, ssh, lzl, lzh;
        F2_UNPACK(kfl, kfh, kf2[pr]);
        F2_UNPACK(gpl, gph, gp2[pr]);
        F2_UNPACK(ssl, ssh, s2[pr]);
        F2_UNPACK(lzl, lzh, lz2[pr]);
        float kfj[2] = {kfl, kfh}, gpj[2] = {gpl, gph};
        float ssj[2] = {ssl, ssh}, lzj[2] = {lzl, lzh};
#pragma unroll
        for (int h = 0; h < 2; ++h) {
            const int j = pr * 2 + h;
            int kk = (int)kfj[h];
            int4 part;
            if (kk > 0) {
                float tf1 = lzj[h] + 1.0f;            // t_first, 1-based local
                int tlast = rows - (int)gpj[h];       // 1-based local
                float sc_ = ssj[h] - tf1 * tf1;
                part = make_int4(kk, start + (int)lzj[h], start + tlast - 1,
                                 __float_as_int(sc_));
            } else {
                part = make_int4(0, 0, 0, 0);
            }
            sp[slice][g * 4 + j] = part;
        }
    }
    __syncthreads();

    if (slice == 0) {
#pragma unroll
        for (int j = 0; j < 4; ++j) {
            const int n = g * 4 + j;
            int4 a = sp[0][n];
            a = comb(a, sp[1][n]);
            a = comb(a, sp[2][n]);
            a = comb(a, sp[3][n]);
            g_partial[(size_t)n * NBLK + blockIdx.x] = a;
        }
    }
}

// One block per neuron: adjacent-pair tree over the 296 block partials.
// Last block to finish also emits the final loss (fused former pass3).
__global__ __launch_bounds__(RED_THREADS) void cv_pass2(const float* __restrict__ target,
                                                        float* __restrict__ out) {
    const int n   = blockIdx.x;
    const int tid = threadIdx.x;

    __shared__ int4 sm[RED_THREADS];

    int4 part = make_int4(0, 0, 0, 0);
    if (tid < NBLK)
        part = g_partial[(size_t)n * NBLK + tid];   // coalesced along chunk axis
    sm[tid] = part;
    __syncthreads();

    for (int lvl = RED_THREADS; lvl > 1; lvl >>= 1) {
        const int half = lvl >> 1;
        int4 res;
        if (tid < half)
            res = comb(sm[2 * tid], sm[2 * tid + 1]);   // adjacent -> contiguous
        __syncthreads();
        if (tid < half)
            sm[tid] = res;
        __syncthreads();
    }

    if (tid == 0) {
        int4 tot = sm[0];
        int kk = tot.x;
        if (kk >= 3) {
            float cnt   = (float)(kk - 1);            // number of ISIs
            float sum_d = (float)(tot.z - tot.y);     // telescoping sum of ISIs
            float mean  = sum_d / cnt;
            if (mean > 0.0f) {
                // sum((d-mean)^2) = sum_d2 - 2*mean*sum_d + cnt*mean^2
                float var = (__int_as_float(tot.w) - 2.0f * mean * sum_d + cnt * mean * mean)
                            / fmaxf(cnt - 1.0f, 1.0f);   // unbiased (correction=1)
                float stdv = (var > 0.0f) ? sqrtf(var) : 0.0f;
                float cv   = stdv / fmaxf(mean, 1e-12f);
                float diff = cv - target[n];
                atomicAdd(&g_accum, diff * diff);
                atomicAdd(&g_cnt, 1);
            }
        }
        // Ticket: the last block to pass here publishes the result.
        __threadfence();
        int t = atomicAdd(&g_ticket, 1);
        if (t == NNEUR - 1) {
            float acc = atomicAdd(&g_accum, 0.0f);    // coherent L2 read
            int   c   = atomicAdd(&g_cnt, 0);
            out[0] = acc / fmaxf((float)c, 1.0f);
        }
    }
}

extern "C" void kernel_launch(void* const* d_in, const int* in_sizes, int n_in,
                              void* d_out, int out_size) {
    const float* spikes = (const float*)d_in[0];   // (16, 2000, 512) float32
    const float* target = (const float*)d_in[1];   // (512,) float32
    float* out = (float*)d_out;                    // scalar float32

    cv_pass1<<<NBLK, 512>>>(spikes);
    cv_pass2<<<NNEUR, RED_THREADS>>>(target, out);
}

// round 15
// speedup vs baseline: 1.0567x; 1.0548x over previous
#include <cuda_runtime.h>
#include <math.h>

// output_spikes (B=16, T=2000, N=512) float32, target_cv (512) float32.
#define NNEUR 512
#define NG    128                  // neuron groups of 4 (float4)
#define LTOT  32000                // B*T
#define NBLK  296                  // 2 blocks/SM, single wave
#define SUBS  (NBLK * 4)           // 1184 sub-chunks (4 row-slices per block)
#define RB    (LTOT / SUBS)        // 27
#define RREM  (LTOT % SUBS)        // 32 (sub-chunks 0..31 get 28 rows)

typedef unsigned long long u64;

// packed {1.0f,1.0f} and {-1.0f,-1.0f}
#define ONE2_C   0x3F8000003F800000ULL
#define NEG12_C  0xBF800000BF800000ULL

#define F2_ADD(o, a, b)    asm("add.rn.f32x2 %0, %1, %2;" : "=l"(o) : "l"(a), "l"(b))
#define F2_MUL(o, a, b)    asm("mul.rn.f32x2 %0, %1, %2;" : "=l"(o) : "l"(a), "l"(b))
#define F2_FMA(o, a, b, c) asm("fma.rn.f32x2 %0, %1, %2, %3;" : "=l"(o) : "l"(a), "l"(b), "l"(c))
#define F2_PACK(o, lo, hi) asm("mov.b64 %0, {%1, %2};" : "=l"(o) : "f"(lo), "f"(hi))
#define F2_UNPACK(lo, hi, in) asm("mov.b64 {%0, %1}, %2;" : "=f"(lo), "=f"(hi) : "l"(in))

// Per-(neuron, block) partial: {k, first_spike_l, last_spike_l, bits(sum_d2)}
__device__ int4  g_partial[NNEUR * NBLK];
__device__ float g_accum;
__device__ int   g_cnt;
__device__ int   g_ticket;

// Ordered combine of two ADJACENT segments (a before b). Identity: k == 0.
__device__ __forceinline__ int4 comb(int4 a, int4 b) {
    if (b.x == 0) return a;
    if (a.x == 0) return b;
    float d = (float)(b.y - a.z);                       // cross-segment ISI
    float s = __int_as_float(a.w) + __int_as_float(b.w) + d * d;
    return make_int4(a.x + b.x, a.y, b.z, __float_as_int(s));
}

// Packed update for one neuron pair p. v in {0,1} per lane.
#define PEP(p, vlo, vhi)                         \
    do {                                         \
        u64 v2_, d2_, m2_, t2_;                  \
        F2_PACK(v2_, (vlo), (vhi));              \
        F2_ADD(d2_, gp2[p], one2);               \
        F2_MUL(m2_, v2_, d2_);                   \
        F2_FMA(s2[p], m2_, d2_, s2[p]);          \
        F2_FMA(gp2[p], m2_, neg12, d2_);         \
        F2_ADD(kf2[p], kf2[p], v2_);             \
        F2_MUL(t2_, v2_, ns2[p]);                \
        F2_FMA(ns2[p], t2_, neg12, ns2[p]);      \
        F2_ADD(lz2[p], lz2[p], ns2[p]);          \
    } while (0)

#define PROW(vec)                      \
    do {                               \
        PEP(0, (vec).x, (vec).y);      \
        PEP(1, (vec).z, (vec).w);      \
    } while (0)

__global__ __launch_bounds__(512, 2) void cvl_scan(const float* __restrict__ x) {
    const int tid   = threadIdx.x;
    const int slice = tid >> 7;          // 0..3 : row-slice within block
    const int g     = tid & (NG - 1);    // 0..127: neuron group (4 neurons)
    const int sc    = blockIdx.x * 4 + slice;      // global sub-chunk
    if (blockIdx.x == 0 && tid == 0) { g_accum = 0.0f; g_cnt = 0; g_ticket = 0; }

    const int start = sc * RB + min(sc, RREM);
    const int rows  = RB + (sc < RREM ? 1 : 0);    // 27 or 28

    const u64 one2  = ONE2_C;
    const u64 neg12 = NEG12_C;
    u64 gp2[2] = {0ULL, 0ULL};
    u64 s2[2]  = {0ULL, 0ULL};
    u64 kf2[2] = {0ULL, 0ULL};
    u64 ns2[2] = {ONE2_C, ONE2_C};
    u64 lz2[2] = {0ULL, 0ULL};

    const float4* p = (const float4*)x + (size_t)start * NG + g;
    int r = 0;

    // prefetch batch 0 (rows >= 27 > 4 always); nc/texture path
    float4 b0 = __ldg(p + 0 * NG), b1 = __ldg(p + 1 * NG);
    float4 b2 = __ldg(p + 2 * NG), b3 = __ldg(p + 3 * NG);
    p += 4 * NG;

    while (r + 8 <= rows) {
        float4 c0 = __ldg(p + 0 * NG), c1 = __ldg(p + 1 * NG);
        float4 c2 = __ldg(p + 2 * NG), c3 = __ldg(p + 3 * NG);
        p += 4 * NG;
        PROW(b0); PROW(b1); PROW(b2); PROW(b3);
        b0 = c0; b1 = c1; b2 = c2; b3 = c3;
        r += 4;
    }
    PROW(b0); PROW(b1); PROW(b2); PROW(b3);
    r += 4;
    for (; r < rows; ++r) {
        float4 v = __ldg(p);
        p += NG;
        PROW(v);
    }

    // Flush: t_first = lz+1, t_last = rows - gp (1-based local);
    // subtract bogus first gap^2 (= t_first^2) from s.
    __shared__ int4 sp[4][NNEUR];
#pragma unroll
    for (int pr = 0; pr < 2; ++pr) {
        float kfl, kfh, gpl, gph, ssl, ssh, lzl, lzh;
        F2_UNPACK(kfl, kfh, kf2[pr]);
        F2_UNPACK(gpl, gph, gp2[pr]);
        F2_UNPACK(ssl, ssh, s2[pr]);
        F2_UNPACK(lzl, lzh, lz2[pr]);
        float kfj[2] = {kfl, kfh}, gpj[2] = {gpl, gph};
        float ssj[2] = {ssl, ssh}, lzj[2] = {lzl, lzh};
#pragma unroll
        for (int h = 0; h < 2; ++h) {
            const int j = pr * 2 + h;
            int kk = (int)kfj[h];
            int4 part;
            if (kk > 0) {
                float tf1 = lzj[h] + 1.0f;            // t_first, 1-based local
                int tlast = rows - (int)gpj[h];       // 1-based local
                float sc_ = ssj[h] - tf1 * tf1;
                part = make_int4(kk, start + (int)lzj[h], start + tlast - 1,
                                 __float_as_int(sc_));
            } else {
                part = make_int4(0, 0, 0, 0);
            }
            sp[slice][g * 4 + j] = part;
        }
    }
    __syncthreads();

    if (slice == 0) {
#pragma unroll
        for (int j = 0; j < 4; ++j) {
            const int n = g * 4 + j;
            int4 a = sp[0][n];
            a = comb(a, sp[1][n]);
            a = comb(a, sp[2][n]);
            a = comb(a, sp[3][n]);
            g_partial[(size_t)n * NBLK + blockIdx.x] = a;
        }
    }
}

// Warp-per-neuron reduction: each lane serially folds a contiguous run of
// partials (lanes 0..7: 10, lanes 8..31: 9 -> 296), then a 5-step shfl tree
// (lane order = segment order, so the ordered combine stays valid).
__global__ __launch_bounds__(256) void cvl_reduce(const float* __restrict__ target,
                                                  float* __restrict__ out) {
    const int wid  = threadIdx.x >> 5;             // warp in block: 0..7
    const int lane = threadIdx.x & 31;
    const int n    = blockIdx.x * 8 + wid;         // neuron

    // contiguous lane partition of 296 = 8*10 + 24*9
    const int cnt   = (lane < 8) ? 10 : 9;
    const int begin = lane * 9 + min(lane, 8);

    const int4* base = &g_partial[(size_t)n * NBLK + begin];
    int4 acc = base[0];
#pragma unroll
    for (int i = 1; i < 9; ++i)
        acc = comb(acc, base[i]);
    if (cnt == 10)
        acc = comb(acc, base[9]);

    // shfl adjacent-pair tree: offsets 1,2,4,8,16
#pragma unroll
    for (int off = 1; off < 32; off <<= 1) {
        int4 other;
        other.x = __shfl_down_sync(0xFFFFFFFFu, acc.x, off);
        other.y = __shfl_down_sync(0xFFFFFFFFu, acc.y, off);
        other.z = __shfl_down_sync(0xFFFFFFFFu, acc.z, off);
        other.w = __shfl_down_sync(0xFFFFFFFFu, acc.w, off);
        int4 res = comb(acc, other);
        if ((lane & (2 * off - 1)) == 0)
            acc = res;
    }

    if (lane == 0) {
        int kk = acc.x;
        if (kk >= 3) {
            float cnt_f = (float)(kk - 1);            // number of ISIs
            float sum_d = (float)(acc.z - acc.y);     // telescoping sum of ISIs
            float mean  = sum_d / cnt_f;
            if (mean > 0.0f) {
                // sum((d-mean)^2) = sum_d2 - 2*mean*sum_d + cnt*mean^2
                float var = (__int_as_float(acc.w) - 2.0f * mean * sum_d + cnt_f * mean * mean)
                            / fmaxf(cnt_f - 1.0f, 1.0f);   // unbiased (correction=1)
                float stdv = (var > 0.0f) ? sqrtf(var) : 0.0f;
                float cv   = stdv / fmaxf(mean, 1e-12f);
                float diff = cv - target[n];
                atomicAdd(&g_accum, diff * diff);
                atomicAdd(&g_cnt, 1);
            }
        }
        // Ticket: the last warp to pass here publishes the result.
        __threadfence();
        int t = atomicAdd(&g_ticket, 1);
        if (t == NNEUR - 1) {
            float acc_s = atomicAdd(&g_accum, 0.0f);   // coherent L2 read
            int   c     = atomicAdd(&g_cnt, 0);
            out[0] = acc_s / fmaxf((float)c, 1.0f);
        }
    }
}

extern "C" void kernel_launch(void* const* d_in, const int* in_sizes, int n_in,
                              void* d_out, int out_size) {
    const float* spikes = (const float*)d_in[0];   // (16, 2000, 512) float32
    const float* target = (const float*)d_in[1];   // (512,) float32
    float* out = (float*)d_out;                    // scalar float32

    cvl_scan<<<NBLK, 512>>>(spikes);
    cvl_reduce<<<NNEUR / 8, 256>>>(target, out);
}